// round 2
// baseline (speedup 1.0000x reference)
#include <cuda_runtime.h>

// BlazeFace decode + weighted NMS (batch 0 only).
// Single block, 128 threads, 7 anchors per thread. All hot state in shared.
//
// Phases:
//   1. zero output, decode dets (boxes+kps+score) for batch 0 into shared
//   2. bitonic sort (1024 slots) of (score desc, idx asc); invalid = -inf
//   3. sequential NMS: pointer-walk the sorted list for "next best";
//      per step each thread IoU-tests its 7 register-resident boxes;
//      common case (n==1) copies the det row from shared; rare case (n>1)
//      does a deterministic 18-quantity tree reduction for the weighted det.

#define NA    896
#define NSORT 1024
#define NT    128
#define PER   7          // NA / NT
#define IOU_T 0.3f
#define MIN_SCORE 0.75f

// dynamic shared layout (in floats)
#define OFF_DET   0                      // NA*17      det rows [ymin,xmin,ymax,xmax,kps...,score]
#define OFF_KEY   (OFF_DET + NA*17)      // NSORT      sort keys
#define OFF_IDX   (OFF_KEY + NSORT)      // NSORT      sort payload (int)
#define OFF_REM   (OFF_IDX + NSORT)      // NA         remaining flags (int)
#define OFF_PART  (OFF_REM + NA)         // NT*18      reduction scratch
#define OFF_FLAG  (OFF_PART + NT*18)     // 2          parity flags (int)
#define SMEM_FLOATS (OFF_FLAG + 2)
#define SMEM_BYTES  (SMEM_FLOATS * 4)

__device__ __forceinline__ float neg_inf() { return __int_as_float(0xff800000); }

__global__ __launch_bounds__(NT, 1)
void blazeface_nms_kernel(const float* __restrict__ raw_boxes,
                          const float* __restrict__ raw_scores,
                          const float* __restrict__ anchors,
                          float* __restrict__ out)
{
    extern __shared__ float smem[];
    float* s_det  = smem + OFF_DET;
    float* s_key  = smem + OFF_KEY;
    int*   s_idx  = (int*)(smem + OFF_IDX);
    int*   s_rem  = (int*)(smem + OFF_REM);
    float* s_part = smem + OFF_PART;
    int*   s_flag = (int*)(smem + OFF_FLAG);

    const int tid = threadIdx.x;
    const float NINF = neg_inf();

    // ---- zero output (harness poisons it) ----
    for (int i = tid; i < NA * 17; i += NT) out[i] = 0.0f;
    if (tid == 0) { s_flag[0] = 0; s_flag[1] = 0; }

    // ---- decode batch 0 ----
    float myb[PER][4];   // my anchors' boxes (registers)
    float myarea[PER];
    float mysc[PER];

    const float inv = 1.0f / 128.0f;
    #pragma unroll
    for (int a = 0; a < PER; ++a) {
        const int i = tid + a * NT;                  // 0..895
        const float4* rb4 = reinterpret_cast<const float4*>(raw_boxes + (size_t)i * 16);
        float4 r0 = rb4[0], r1 = rb4[1], r2 = rb4[2], r3 = rb4[3];
        float4 an = reinterpret_cast<const float4*>(anchors)[i];
        const float ax = an.x, ay = an.y, aw = an.z, ah = an.w;

        float xc = r0.x * inv * aw + ax;
        float yc = r0.y * inv * ah + ay;
        float w  = r0.z * inv * aw;
        float h  = r0.w * inv * ah;
        float c0 = yc - h * 0.5f;
        float c1 = xc - w * 0.5f;
        float c2 = yc + h * 0.5f;
        float c3 = xc + w * 0.5f;

        float det[17];
        det[0] = c0; det[1] = c1; det[2] = c2; det[3] = c3;
        // keypoints: raw[4::2]->x, raw[5::2]->y, interleaved
        det[4]  = r1.x * inv * aw + ax;  det[5]  = r1.y * inv * ah + ay;
        det[6]  = r1.z * inv * aw + ax;  det[7]  = r1.w * inv * ah + ay;
        det[8]  = r2.x * inv * aw + ax;  det[9]  = r2.y * inv * ah + ay;
        det[10] = r2.z * inv * aw + ax;  det[11] = r2.w * inv * ah + ay;
        det[12] = r3.x * inv * aw + ax;  det[13] = r3.y * inv * ah + ay;
        det[14] = r3.z * inv * aw + ax;  det[15] = r3.w * inv * ah + ay;

        float x = raw_scores[i];
        x = fminf(fmaxf(x, -100.0f), 100.0f);
        float sc = 1.0f / (1.0f + expf(-x));
        det[16] = sc;

        #pragma unroll
        for (int c = 0; c < 17; ++c) s_det[i * 17 + c] = det[c];

        bool valid = (sc >= MIN_SCORE);
        s_rem[i] = valid ? 1 : 0;
        s_key[i] = valid ? sc : NINF;
        s_idx[i] = i;

        myb[a][0] = c0; myb[a][1] = c1; myb[a][2] = c2; myb[a][3] = c3;
        myarea[a] = (c2 - c0) * (c3 - c1);
        mysc[a]   = sc;
    }
    // pad sort slots
    for (int i = NA + tid; i < NSORT; i += NT) { s_key[i] = NINF; s_idx[i] = NSORT + i; }
    __syncthreads();

    // ---- bitonic sort: descending by key, ties ascending by idx ----
    for (int k = 2; k <= NSORT; k <<= 1) {
        for (int j = k >> 1; j > 0; j >>= 1) {
            #pragma unroll
            for (int q = 0; q < NSORT / NT; ++q) {
                int i = tid + q * NT;
                int ixj = i ^ j;
                if (ixj > i) {
                    float ki = s_key[i], kj = s_key[ixj];
                    int   ii = s_idx[i], ij = s_idx[ixj];
                    // i "before" ixj in descending order?
                    bool before = (ki > kj) || (ki == kj && ii < ij);
                    bool dirUp  = ((i & k) == 0);
                    bool doSwap = dirUp ? !before : before;
                    if (doSwap) {
                        s_key[i] = kj; s_key[ixj] = ki;
                        s_idx[i] = ij; s_idx[ixj] = ii;
                    }
                }
            }
            __syncthreads();
        }
    }

    // ---- sequential weighted NMS ----
    int count = 0;
    int p = 0;
    int iter = 0;
    while (true) {
        // all threads redundantly (deterministically) find next best
        int best = -1;
        while (p < NSORT) {
            if (s_key[p] == NINF) break;           // rest are invalid
            int cand = s_idx[p];
            if (s_rem[cand]) { best = cand; break; }
            ++p;
        }
        if (best < 0) break;

        const float b0 = s_det[best * 17 + 0], b1 = s_det[best * 17 + 1];
        const float b2 = s_det[best * 17 + 2], b3 = s_det[best * 17 + 3];
        const float areaB = (b2 - b0) * (b3 - b1);

        const int slot = iter & 1;
        int  ovmask = 0;
        bool other  = false;
        #pragma unroll
        for (int a = 0; a < PER; ++a) {
            const int i = tid + a * NT;
            if (s_rem[i]) {
                float iy = fminf(b2, myb[a][2]) - fmaxf(b0, myb[a][0]);
                float ix = fminf(b3, myb[a][3]) - fmaxf(b1, myb[a][1]);
                iy = fmaxf(iy, 0.0f);
                ix = fmaxf(ix, 0.0f);
                float inter = iy * ix;
                float iou = inter / (areaB + myarea[a] - inter);   // NaN -> compare false
                if (iou > IOU_T) {
                    s_rem[i] = 0;
                    ovmask |= (1 << a);
                    if (i != best) other = true;
                }
            }
        }
        if (tid == 0) {
            s_rem[best] = 0;        // ensure best removed (degenerate/NaN case)
            s_flag[slot ^ 1] = 0;   // pre-clear next iteration's flag (safe: last
                                    // read of that slot was before prev end barrier)
        }
        if (other) s_flag[slot] = 1;  // benign race: identical value
        __syncthreads();              // (A) rem/flag visible

        const bool rare = (s_flag[slot] != 0);

        if (rare) {
            // exact n / total / weighted coords via deterministic tree reduction
            float acc[18];
            #pragma unroll
            for (int q = 0; q < 18; ++q) acc[q] = 0.0f;
            #pragma unroll
            for (int a = 0; a < PER; ++a) {
                if (ovmask & (1 << a)) {
                    const int i = tid + a * NT;
                    const float s = mysc[a];
                    #pragma unroll
                    for (int c = 0; c < 16; ++c) acc[c] += s * s_det[i * 17 + c];
                    acc[16] += s;      // total score
                    acc[17] += 1.0f;   // n
                }
            }
            #pragma unroll
            for (int q = 0; q < 18; ++q) s_part[tid * 18 + q] = acc[q];
            __syncthreads();
            for (int s = NT / 2; s > 0; s >>= 1) {
                if (tid < s) {
                    #pragma unroll
                    for (int q = 0; q < 18; ++q)
                        s_part[tid * 18 + q] += s_part[(tid + s) * 18 + q];
                }
                __syncthreads();
            }
            const float total = s_part[16];
            const float n     = s_part[17];
            if (n > 1.5f) {
                if (tid < 16)
                    out[count * 17 + tid] = s_part[tid] / (total > 0.0f ? total : 1.0f);
                if (tid == 16)
                    out[count * 17 + 16] = total / fmaxf(n, 1.0f);
            } else {
                if (tid < 17) out[count * 17 + tid] = s_det[best * 17 + tid];
            }
        } else {
            // common path: n == 1, wdet = det[best]
            if (tid < 17) out[count * 17 + tid] = s_det[best * 17 + tid];
        }
        ++count;
        ++iter;
        __syncthreads();   // (B) rem/out settled before next pointer walk
    }
}

extern "C" void kernel_launch(void* const* d_in, const int* in_sizes, int n_in,
                              void* d_out, int out_size) {
    // identify inputs by size (robust to ordering):
    //   raw_boxes: 2048*896*16 = 29360128, raw_scores: 2048*896 = 1835008, anchors: 896*4 = 3584
    const float* raw_boxes  = nullptr;
    const float* raw_scores = nullptr;
    const float* anchors    = nullptr;
    for (int i = 0; i < n_in; ++i) {
        if (in_sizes[i] == NA * 4)            anchors    = (const float*)d_in[i];
        else if (in_sizes[i] == 2048 * NA)    raw_scores = (const float*)d_in[i];
        else                                  raw_boxes  = (const float*)d_in[i];
    }
    cudaFuncSetAttribute(blazeface_nms_kernel,
                         cudaFuncAttributeMaxDynamicSharedMemorySize, SMEM_BYTES);
    blazeface_nms_kernel<<<1, NT, SMEM_BYTES>>>(raw_boxes, raw_scores, anchors, (float*)d_out);
}

// round 9
// speedup vs baseline: 5.0485x; 5.0485x over previous
#include <cuda_runtime.h>

// BlazeFace decode + weighted NMS (batch 0 only), mask-matrix formulation.
// Single block, 128 threads.
//
// Phases:
//   1. decode 896 dets into shared; zero output
//   2. compact valid dets (block prefix sum), bitonic-sort (score desc, idx asc)
//      over P = next_pow2(V) slots
//   3. build VxV overlap bit-matrix in parallel (row per thread, division-free)
//   4. thread-0 serial scan over bitmasks (no barriers, no divergence):
//      pick first remaining bit, clear its overlap row, record selection;
//      rare n>1 case: serial weighted merge written back into shared det row
//   5. parallel copy of selected rows to out

#define NA    896
#define NT    128
#define PER   7           // NA / NT
#define WMAX  28          // ceil(NA/32)
#define IOU_T 0.3f
#define MIN_SCORE 0.75f

// shared layout in 4-byte units
#define OFF_DET    0                        // NA*17  det rows
#define OFF_KEY    (OFF_DET  + NA*17)       // 1024   sort keys
#define OFF_SIDX   (OFF_KEY  + 1024)        // 1024   sorted anchor idx (int)
#define OFF_SBOX   (OFF_SIDX + 1024)        // NA*4   per-sorted-pos boxes (16B aligned)
#define OFF_SAREA  (OFF_SBOX + NA*4)        // NA     per-sorted-pos areas
#define OFF_MASK   (OFF_SAREA + NA)         // NA*WMAX overlap bits (int)
#define OFF_REMW   (OFF_MASK + NA*WMAX)     // WMAX   remaining words (int)
#define OFF_SEL    (OFF_REMW + WMAX)        // NA     selected anchor idx (int)
#define OFF_OV     (OFF_SEL  + NA)          // WMAX   overlap scratch (int)
#define OFF_WSUM   (OFF_OV   + WMAX)        // 4      warp scan sums (int)
#define OFF_MISC   (OFF_WSUM + 4)           // 2      [V, count] (int)
#define SMEM_UNITS (OFF_MISC + 2)
#define SMEM_BYTES (SMEM_UNITS * 4)

__device__ __forceinline__ float neg_inf() { return __int_as_float(0xff800000); }

__global__ __launch_bounds__(NT, 1)
void blazeface_nms_kernel(const float* __restrict__ raw_boxes,
                          const float* __restrict__ raw_scores,
                          const float* __restrict__ anchors,
                          float* __restrict__ out)
{
    extern __shared__ float smem[];
    float* s_det   = smem + OFF_DET;
    float* s_key   = smem + OFF_KEY;
    int*   s_sidx  = (int*)(smem + OFF_SIDX);
    float4* s_sbox = (float4*)(smem + OFF_SBOX);
    float* s_sarea = smem + OFF_SAREA;
    int*   s_mask  = (int*)(smem + OFF_MASK);
    unsigned* s_remw = (unsigned*)(smem + OFF_REMW);
    int*   s_sel   = (int*)(smem + OFF_SEL);
    unsigned* s_ov = (unsigned*)(smem + OFF_OV);
    int*   s_wsum  = (int*)(smem + OFF_WSUM);
    int*   s_misc  = (int*)(smem + OFF_MISC);   // [0]=V, [1]=count

    const int tid  = threadIdx.x;
    const int lane = tid & 31;
    const int wrp  = tid >> 5;
    const float NINF = neg_inf();

    // ---- zero output (harness poisons it) ----
    for (int i = tid; i < NA * 17; i += NT) out[i] = 0.0f;

    // ---- phase 1: decode batch 0 into shared ----
    const float inv = 1.0f / 128.0f;
    #pragma unroll
    for (int a = 0; a < PER; ++a) {
        const int i = tid + a * NT;                  // 0..895
        const float4* rb4 = reinterpret_cast<const float4*>(raw_boxes + (size_t)i * 16);
        float4 r0 = rb4[0], r1 = rb4[1], r2 = rb4[2], r3 = rb4[3];
        float4 an = reinterpret_cast<const float4*>(anchors)[i];
        const float ax = an.x, ay = an.y, aw = an.z, ah = an.w;

        float xc = r0.x * inv * aw + ax;
        float yc = r0.y * inv * ah + ay;
        float w  = r0.z * inv * aw;
        float h  = r0.w * inv * ah;

        float* d = s_det + i * 17;
        d[0]  = yc - h * 0.5f;
        d[1]  = xc - w * 0.5f;
        d[2]  = yc + h * 0.5f;
        d[3]  = xc + w * 0.5f;
        d[4]  = r1.x * inv * aw + ax;  d[5]  = r1.y * inv * ah + ay;
        d[6]  = r1.z * inv * aw + ax;  d[7]  = r1.w * inv * ah + ay;
        d[8]  = r2.x * inv * aw + ax;  d[9]  = r2.y * inv * ah + ay;
        d[10] = r2.z * inv * aw + ax;  d[11] = r2.w * inv * ah + ay;
        d[12] = r3.x * inv * aw + ax;  d[13] = r3.y * inv * ah + ay;
        d[14] = r3.z * inv * aw + ax;  d[15] = r3.w * inv * ah + ay;

        float x = raw_scores[i];
        x = fminf(fmaxf(x, -100.0f), 100.0f);
        d[16] = 1.0f / (1.0f + expf(-x));           // precise sigmoid
    }
    __syncthreads();

    // ---- phase 2a: compact valid dets (stable by anchor idx) ----
    const int base = tid * PER;
    int vmask = 0, cnt = 0;
    #pragma unroll
    for (int a = 0; a < PER; ++a) {
        bool v = (s_det[(base + a) * 17 + 16] >= MIN_SCORE);
        vmask |= (int)v << a;
        cnt += (int)v;
    }
    int incl = cnt;
    #pragma unroll
    for (int d = 1; d < 32; d <<= 1) {
        int v = __shfl_up_sync(0xffffffffu, incl, d);
        if (lane >= d) incl += v;
    }
    if (lane == 31) s_wsum[wrp] = incl;
    __syncthreads();
    if (tid == 0) {
        int s = 0;
        #pragma unroll
        for (int w = 0; w < 4; ++w) { int t = s_wsum[w]; s_wsum[w] = s; s += t; }
        s_misc[0] = s;     // V
    }
    __syncthreads();
    const int V = s_misc[0];

    if (V > 0) {
        int off = s_wsum[wrp] + incl - cnt;          // exclusive offset
        #pragma unroll
        for (int a = 0; a < PER; ++a) {
            if (vmask & (1 << a)) {
                const int anc = base + a;
                s_key[off]  = s_det[anc * 17 + 16];
                s_sidx[off] = anc;
                ++off;
            }
        }

        int P = 2;
        while (P < V) P <<= 1;                       // next pow2 >= V (<=1024)
        for (int i = V + tid; i < P; i += NT) { s_key[i] = NINF; s_sidx[i] = 100000 + i; }
        __syncthreads();

        // ---- phase 2b: bitonic sort (score desc, idx asc) ----
        for (int k = 2; k <= P; k <<= 1) {
            for (int j = k >> 1; j > 0; j >>= 1) {
                for (int i = tid; i < P; i += NT) {
                    int ixj = i ^ j;
                    if (ixj > i) {
                        float ki = s_key[i], kj = s_key[ixj];
                        int   ii = s_sidx[i], ij = s_sidx[ixj];
                        bool before = (ki > kj) || (ki == kj && ii < ij);
                        bool dirUp  = ((i & k) == 0);
                        if (dirUp ? !before : before) {
                            s_key[i] = kj; s_key[ixj] = ki;
                            s_sidx[i] = ij; s_sidx[ixj] = ii;
                        }
                    }
                }
                __syncthreads();
            }
        }

        // ---- phase 3a: gather per-sorted-pos boxes/areas ----
        const int W = (V + 31) >> 5;
        for (int pos = tid; pos < V; pos += NT) {
            const int anc = s_sidx[pos];
            float c0 = s_det[anc * 17 + 0], c1 = s_det[anc * 17 + 1];
            float c2 = s_det[anc * 17 + 2], c3 = s_det[anc * 17 + 3];
            s_sbox[pos] = make_float4(c0, c1, c2, c3);
            s_sarea[pos] = (c2 - c0) * (c3 - c1);
        }
        // init remaining words
        for (int w = tid; w < W; w += NT) {
            int rb = V - (w << 5);
            s_remw[w] = (rb >= 32) ? 0xffffffffu : ((1u << rb) - 1u);
        }
        __syncthreads();

        // ---- phase 3b: overlap bit-matrix (row per thread) ----
        for (int row = tid; row < V; row += NT) {
            const float4 b = s_sbox[row];
            const float areaA = s_sarea[row];
            unsigned word = 0;
            for (int j = 0; j < V; ++j) {
                const float4 c = s_sbox[j];
                float iy = fminf(b.z, c.z) - fmaxf(b.x, c.x);
                float ix = fminf(b.w, c.w) - fmaxf(b.y, c.y);
                iy = fmaxf(iy, 0.0f); ix = fmaxf(ix, 0.0f);
                float inter = iy * ix;
                float uni   = areaA + s_sarea[j] - inter;
                // iou > T  <=>  inter > T*uni   (uni>=0; uni==0 -> false, matches NaN>T)
                bool ov = (inter > IOU_T * uni);
                word |= (unsigned)ov << (j & 31);
                if ((j & 31) == 31) { s_mask[row * W + (j >> 5)] = (int)word; word = 0; }
            }
            if (V & 31) s_mask[row * W + (V >> 5)] = (int)word;
        }
        __syncthreads();

        // ---- phase 4: serial scan (thread 0 only; no barriers inside) ----
        if (tid == 0) {
            int count = 0, w0 = 0;
            while (true) {
                while (w0 < W && s_remw[w0] == 0u) ++w0;
                if (w0 >= W) break;
                const unsigned rw = s_remw[w0];
                const int b   = __ffs(rw) - 1;
                const int pos = (w0 << 5) + b;
                const int* mrow = s_mask + pos * W;
                int n = 0;
                for (int w = w0; w < W; ++w) {
                    unsigned m = (unsigned)mrow[w] & s_remw[w];
                    s_ov[w] = m;
                    n += __popc(m);
                    s_remw[w] &= ~(unsigned)mrow[w];
                }
                s_remw[w0] &= ~(1u << b);            // ensure best removed
                const int bestAnc = s_sidx[pos];
                if (n > 1) {
                    float acc[16];
                    #pragma unroll
                    for (int c = 0; c < 16; ++c) acc[c] = 0.0f;
                    float tot = 0.0f;
                    for (int w = w0; w < W; ++w) {
                        unsigned m = s_ov[w];
                        while (m) {
                            int bb = __ffs(m) - 1; m &= m - 1;
                            const int anc2 = s_sidx[(w << 5) + bb];
                            const float s = s_det[anc2 * 17 + 16];
                            #pragma unroll
                            for (int c = 0; c < 16; ++c) acc[c] += s * s_det[anc2 * 17 + c];
                            tot += s;
                        }
                    }
                    const float denom = (tot > 0.0f) ? tot : 1.0f;
                    #pragma unroll
                    for (int c = 0; c < 16; ++c) s_det[bestAnc * 17 + c] = acc[c] / denom;
                    s_det[bestAnc * 17 + 16] = tot / (float)(n > 1 ? n : 1);
                }
                s_sel[count++] = bestAnc;
            }
            s_misc[1] = count;
        }
        __syncthreads();

        // ---- phase 5: parallel copy of selected rows ----
        const int count = s_misc[1];
        for (int e = tid; e < count * 17; e += NT) {
            const int k = e / 17, c = e - k * 17;
            out[e] = s_det[s_sel[k] * 17 + c];
        }
    }
}

extern "C" void kernel_launch(void* const* d_in, const int* in_sizes, int n_in,
                              void* d_out, int out_size) {
    // identify inputs by size (robust to ordering):
    //   raw_boxes: 2048*896*16, raw_scores: 2048*896, anchors: 896*4
    const float* raw_boxes  = nullptr;
    const float* raw_scores = nullptr;
    const float* anchors    = nullptr;
    for (int i = 0; i < n_in; ++i) {
        if (in_sizes[i] == NA * 4)            anchors    = (const float*)d_in[i];
        else if (in_sizes[i] == 2048 * NA)    raw_scores = (const float*)d_in[i];
        else                                  raw_boxes  = (const float*)d_in[i];
    }
    cudaFuncSetAttribute(blazeface_nms_kernel,
                         cudaFuncAttributeMaxDynamicSharedMemorySize, SMEM_BYTES);
    blazeface_nms_kernel<<<1, NT, SMEM_BYTES>>>(raw_boxes, raw_scores, anchors, (float*)d_out);
}

// round 12
// speedup vs baseline: 7.4712x; 1.4799x over previous
#include <cuda_runtime.h>

// BlazeFace decode + weighted NMS (batch 0 only), mask-matrix formulation.
// Single block, 128 threads.
//
// Phases:
//   1. decode 896 dets into shared; zero output
//   2. compact valid dets (block prefix sum), bitonic-sort (score desc, idx asc)
//   3. build VxV overlap bit-matrix in parallel (row per thread, division-free)
//   4. WARP-REGISTER scan (warp 0): remaining-set lives in registers, lane k
//      owns word k (W <= 28 <= 32). Per step: ballot -> first word, shfl
//      broadcast, one parallel LDS of the mask row, register AND-NOT, ballot
//      for the rare n>1 flag. No shared-memory round-trips on the chain.
//   5. parallel copy of selected rows to out

#define NA    896
#define NT    128
#define PER   7           // NA / NT
#define WMAX  28          // ceil(NA/32)
#define IOU_T 0.3f
#define MIN_SCORE 0.75f
#define FULLM 0xffffffffu

// shared layout in 4-byte units
#define OFF_DET    0                        // NA*17  det rows
#define OFF_KEY    (OFF_DET  + NA*17)       // 1024   sort keys
#define OFF_SIDX   (OFF_KEY  + 1024)        // 1024   sorted anchor idx (int)
#define OFF_SBOX   (OFF_SIDX + 1024)        // NA*4   per-sorted-pos boxes (16B aligned)
#define OFF_SAREA  (OFF_SBOX + NA*4)        // NA     per-sorted-pos areas
#define OFF_MASK   (OFF_SAREA + NA)         // NA*WMAX overlap bits (int)
#define OFF_SEL    (OFF_MASK + NA*WMAX)     // NA     selected anchor idx (int)
#define OFF_OV     (OFF_SEL  + NA)          // WMAX   overlap scratch (int)
#define OFF_WSUM   (OFF_OV   + WMAX)        // 4      warp scan sums (int)
#define OFF_MISC   (OFF_WSUM + 4)           // 2      [V, count] (int)
#define SMEM_UNITS (OFF_MISC + 2)
#define SMEM_BYTES (SMEM_UNITS * 4)

__device__ __forceinline__ float neg_inf() { return __int_as_float(0xff800000); }

__global__ __launch_bounds__(NT, 1)
void blazeface_nms_kernel(const float* __restrict__ raw_boxes,
                          const float* __restrict__ raw_scores,
                          const float* __restrict__ anchors,
                          float* __restrict__ out)
{
    extern __shared__ float smem[];
    float* s_det   = smem + OFF_DET;
    float* s_key   = smem + OFF_KEY;
    int*   s_sidx  = (int*)(smem + OFF_SIDX);
    float4* s_sbox = (float4*)(smem + OFF_SBOX);
    float* s_sarea = smem + OFF_SAREA;
    unsigned* s_mask = (unsigned*)(smem + OFF_MASK);
    int*   s_sel   = (int*)(smem + OFF_SEL);
    unsigned* s_ov = (unsigned*)(smem + OFF_OV);
    int*   s_wsum  = (int*)(smem + OFF_WSUM);
    int*   s_misc  = (int*)(smem + OFF_MISC);   // [0]=V, [1]=count

    const int tid  = threadIdx.x;
    const int lane = tid & 31;
    const int wrp  = tid >> 5;
    const float NINF = neg_inf();

    // ---- zero output (harness poisons it) ----
    for (int i = tid; i < NA * 17; i += NT) out[i] = 0.0f;

    // ---- phase 1: decode batch 0 into shared ----
    const float inv = 1.0f / 128.0f;
    #pragma unroll
    for (int a = 0; a < PER; ++a) {
        const int i = tid + a * NT;                  // 0..895
        const float4* rb4 = reinterpret_cast<const float4*>(raw_boxes + (size_t)i * 16);
        float4 r0 = rb4[0], r1 = rb4[1], r2 = rb4[2], r3 = rb4[3];
        float4 an = reinterpret_cast<const float4*>(anchors)[i];
        const float ax = an.x, ay = an.y, aw = an.z, ah = an.w;

        float xc = r0.x * inv * aw + ax;
        float yc = r0.y * inv * ah + ay;
        float w  = r0.z * inv * aw;
        float h  = r0.w * inv * ah;

        float* d = s_det + i * 17;
        d[0]  = yc - h * 0.5f;
        d[1]  = xc - w * 0.5f;
        d[2]  = yc + h * 0.5f;
        d[3]  = xc + w * 0.5f;
        d[4]  = r1.x * inv * aw + ax;  d[5]  = r1.y * inv * ah + ay;
        d[6]  = r1.z * inv * aw + ax;  d[7]  = r1.w * inv * ah + ay;
        d[8]  = r2.x * inv * aw + ax;  d[9]  = r2.y * inv * ah + ay;
        d[10] = r2.z * inv * aw + ax;  d[11] = r2.w * inv * ah + ay;
        d[12] = r3.x * inv * aw + ax;  d[13] = r3.y * inv * ah + ay;
        d[14] = r3.z * inv * aw + ax;  d[15] = r3.w * inv * ah + ay;

        float x = raw_scores[i];
        x = fminf(fmaxf(x, -100.0f), 100.0f);
        d[16] = 1.0f / (1.0f + expf(-x));           // precise sigmoid
    }
    __syncthreads();

    // ---- phase 2a: compact valid dets (stable by anchor idx) ----
    const int base = tid * PER;
    int vmask = 0, cnt = 0;
    #pragma unroll
    for (int a = 0; a < PER; ++a) {
        bool v = (s_det[(base + a) * 17 + 16] >= MIN_SCORE);
        vmask |= (int)v << a;
        cnt += (int)v;
    }
    int incl = cnt;
    #pragma unroll
    for (int d = 1; d < 32; d <<= 1) {
        int v = __shfl_up_sync(FULLM, incl, d);
        if (lane >= d) incl += v;
    }
    if (lane == 31) s_wsum[wrp] = incl;
    __syncthreads();
    if (tid == 0) {
        int s = 0;
        #pragma unroll
        for (int w = 0; w < 4; ++w) { int t = s_wsum[w]; s_wsum[w] = s; s += t; }
        s_misc[0] = s;     // V
    }
    __syncthreads();
    const int V = s_misc[0];

    if (V > 0) {
        int off = s_wsum[wrp] + incl - cnt;          // exclusive offset
        #pragma unroll
        for (int a = 0; a < PER; ++a) {
            if (vmask & (1 << a)) {
                const int anc = base + a;
                s_key[off]  = s_det[anc * 17 + 16];
                s_sidx[off] = anc;
                ++off;
            }
        }

        int P = 2;
        while (P < V) P <<= 1;                       // next pow2 >= V (<=1024)
        for (int i = V + tid; i < P; i += NT) { s_key[i] = NINF; s_sidx[i] = 100000 + i; }
        __syncthreads();

        // ---- phase 2b: bitonic sort (score desc, idx asc) ----
        for (int k = 2; k <= P; k <<= 1) {
            for (int j = k >> 1; j > 0; j >>= 1) {
                for (int i = tid; i < P; i += NT) {
                    int ixj = i ^ j;
                    if (ixj > i) {
                        float ki = s_key[i], kj = s_key[ixj];
                        int   ii = s_sidx[i], ij = s_sidx[ixj];
                        bool before = (ki > kj) || (ki == kj && ii < ij);
                        bool dirUp  = ((i & k) == 0);
                        if (dirUp ? !before : before) {
                            s_key[i] = kj; s_key[ixj] = ki;
                            s_sidx[i] = ij; s_sidx[ixj] = ii;
                        }
                    }
                }
                __syncthreads();
            }
        }

        // ---- phase 3a: gather per-sorted-pos boxes/areas ----
        const int W = (V + 31) >> 5;
        for (int pos = tid; pos < V; pos += NT) {
            const int anc = s_sidx[pos];
            float c0 = s_det[anc * 17 + 0], c1 = s_det[anc * 17 + 1];
            float c2 = s_det[anc * 17 + 2], c3 = s_det[anc * 17 + 3];
            s_sbox[pos] = make_float4(c0, c1, c2, c3);
            s_sarea[pos] = (c2 - c0) * (c3 - c1);
        }
        __syncthreads();

        // ---- phase 3b: overlap bit-matrix (row per thread) ----
        for (int row = tid; row < V; row += NT) {
            const float4 b = s_sbox[row];
            const float areaA = s_sarea[row];
            unsigned word = 0;
            for (int j = 0; j < V; ++j) {
                const float4 c = s_sbox[j];
                float iy = fminf(b.z, c.z) - fmaxf(b.x, c.x);
                float ix = fminf(b.w, c.w) - fmaxf(b.y, c.y);
                iy = fmaxf(iy, 0.0f); ix = fmaxf(ix, 0.0f);
                float inter = iy * ix;
                float uni   = areaA + s_sarea[j] - inter;
                // iou > T  <=>  inter > T*uni   (uni>=0; uni==0 -> false, matches NaN>T)
                bool ov = (inter > IOU_T * uni);
                word |= (unsigned)ov << (j & 31);
                if ((j & 31) == 31) { s_mask[row * W + (j >> 5)] = word; word = 0; }
            }
            if (V & 31) s_mask[row * W + (V >> 5)] = word;
        }
        __syncthreads();

        // ---- phase 4: warp-register scan (warp 0 only) ----
        if (wrp == 0) {
            // lane k owns remaining word k (k < W <= 28)
            unsigned rem = 0;
            if (lane < W) {
                int rb = V - (lane << 5);
                rem = (rb >= 32) ? FULLM : ((1u << rb) - 1u);
            }
            int count = 0;
            while (true) {
                unsigned nz = __ballot_sync(FULLM, rem != 0u);
                if (nz == 0u) break;
                const int w0  = __ffs(nz) - 1;
                const unsigned rw = __shfl_sync(FULLM, rem, w0);
                const int b   = __ffs(rw) - 1;
                const int pos = (w0 << 5) + b;

                // parallel mask-row load (one LDS per lane)
                unsigned mrow = (lane < W) ? s_mask[pos * W + lane] : 0u;
                unsigned ovw  = mrow & rem;
                rem &= ~mrow;
                if (lane == w0) rem &= ~(1u << b);   // ensure best removed

                // non-self overlap?
                unsigned ov_noself = ovw;
                if (lane == w0) ov_noself &= ~(1u << b);
                const unsigned anyov = __ballot_sync(FULLM, ov_noself != 0u);

                if (anyov) {
                    // rare path: exact n; merge if n > 1
                    const int n = (int)__reduce_add_sync(FULLM, (unsigned)__popc(ovw));
                    if (lane < W) s_ov[lane] = ovw;
                    __syncwarp(FULLM);
                    if (n > 1 && lane == 0) {
                        const int bestAnc = s_sidx[pos];
                        float acc[16];
                        #pragma unroll
                        for (int c = 0; c < 16; ++c) acc[c] = 0.0f;
                        float tot = 0.0f;
                        for (int w = 0; w < W; ++w) {
                            unsigned m = s_ov[w];
                            while (m) {
                                int bb = __ffs(m) - 1; m &= m - 1;
                                const int anc2 = s_sidx[(w << 5) + bb];
                                const float s = s_det[anc2 * 17 + 16];
                                #pragma unroll
                                for (int c = 0; c < 16; ++c) acc[c] += s * s_det[anc2 * 17 + c];
                                tot += s;
                            }
                        }
                        const float denom = (tot > 0.0f) ? tot : 1.0f;
                        #pragma unroll
                        for (int c = 0; c < 16; ++c) s_det[bestAnc * 17 + c] = acc[c] / denom;
                        s_det[bestAnc * 17 + 16] = tot / (float)n;
                    }
                    __syncwarp(FULLM);               // s_ov settled before next overwrite
                }

                if (lane == 0) s_sel[count] = s_sidx[pos];
                ++count;
            }
            if (lane == 0) s_misc[1] = count;
        }
        __syncthreads();

        // ---- phase 5: parallel copy of selected rows ----
        const int count = s_misc[1];
        for (int e = tid; e < count * 17; e += NT) {
            const int k = e / 17, c = e - k * 17;
            out[e] = s_det[s_sel[k] * 17 + c];
        }
    }
}

extern "C" void kernel_launch(void* const* d_in, const int* in_sizes, int n_in,
                              void* d_out, int out_size) {
    // identify inputs by size (robust to ordering):
    //   raw_boxes: 2048*896*16, raw_scores: 2048*896, anchors: 896*4
    const float* raw_boxes  = nullptr;
    const float* raw_scores = nullptr;
    const float* anchors    = nullptr;
    for (int i = 0; i < n_in; ++i) {
        if (in_sizes[i] == NA * 4)            anchors    = (const float*)d_in[i];
        else if (in_sizes[i] == 2048 * NA)    raw_scores = (const float*)d_in[i];
        else                                  raw_boxes  = (const float*)d_in[i];
    }
    cudaFuncSetAttribute(blazeface_nms_kernel,
                         cudaFuncAttributeMaxDynamicSharedMemorySize, SMEM_BYTES);
    blazeface_nms_kernel<<<1, NT, SMEM_BYTES>>>(raw_boxes, raw_scores, anchors, (float*)d_out);
}

// round 15
// speedup vs baseline: 8.0967x; 1.0837x over previous
#include <cuda_runtime.h>

// BlazeFace decode + weighted NMS (batch 0 only), mask-matrix formulation.
// Single block, 128 threads. DEFERRED DECODE: only valid (score>=0.75)
// anchors are decoded, after the sort, indexed by sorted position.
//
// Phases:
//   1. sigmoid scores only; validity mask; block prefix-sum compaction
//   2. bitonic sort (score desc, anchor idx asc) over P = next_pow2(V)
//   3a. decode ONLY the V sorted dets (gathered raw_boxes loads)
//   3b. build VxV overlap bit-matrix in parallel (division-free)
//   4. warp-register scan (warp 0): remaining-set in registers, lane k owns
//      word k; ballot -> shfl -> one parallel LDS -> register AND-NOT per step
//   5. parallel copy of selected rows to out

#define NA    896
#define NT    128
#define PER   7           // NA / NT
#define WMAX  28          // ceil(NA/32)
#define IOU_T 0.3f
#define MIN_SCORE 0.75f
#define FULLM 0xffffffffu

// shared layout in 4-byte units (s_det indexed by SORTED POSITION now)
#define OFF_DET    0                        // NA*17  det rows (pos-indexed)
#define OFF_KEY    (OFF_DET  + NA*17)       // 1024   sort keys
#define OFF_SIDX   (OFF_KEY  + 1024)        // 1024   anchor idx (int)
#define OFF_SBOX   (OFF_SIDX + 1024)        // NA*4   per-pos boxes (16B aligned)
#define OFF_SAREA  (OFF_SBOX + NA*4)        // NA     per-pos areas
#define OFF_MASK   (OFF_SAREA + NA)         // NA*WMAX overlap bits
#define OFF_SEL    (OFF_MASK + NA*WMAX)     // NA     selected pos (int)
#define OFF_OV     (OFF_SEL  + NA)          // WMAX   overlap scratch
#define OFF_WSUM   (OFF_OV   + WMAX)        // 4      warp scan sums (int)
#define OFF_MISC   (OFF_WSUM + 4)           // 2      [V, count] (int)
#define SMEM_UNITS (OFF_MISC + 2)
#define SMEM_BYTES (SMEM_UNITS * 4)

__device__ __forceinline__ float neg_inf() { return __int_as_float(0xff800000); }

__global__ __launch_bounds__(NT, 1)
void blazeface_nms_kernel(const float* __restrict__ raw_boxes,
                          const float* __restrict__ raw_scores,
                          const float* __restrict__ anchors,
                          float* __restrict__ out)
{
    extern __shared__ float smem[];
    float* s_det   = smem + OFF_DET;
    float* s_key   = smem + OFF_KEY;
    int*   s_sidx  = (int*)(smem + OFF_SIDX);
    float4* s_sbox = (float4*)(smem + OFF_SBOX);
    float* s_sarea = smem + OFF_SAREA;
    unsigned* s_mask = (unsigned*)(smem + OFF_MASK);
    int*   s_sel   = (int*)(smem + OFF_SEL);
    unsigned* s_ov = (unsigned*)(smem + OFF_OV);
    int*   s_wsum  = (int*)(smem + OFF_WSUM);
    int*   s_misc  = (int*)(smem + OFF_MISC);   // [0]=V, [1]=count

    const int tid  = threadIdx.x;
    const int lane = tid & 31;
    const int wrp  = tid >> 5;
    const float NINF = neg_inf();

    // ---- zero output (harness poisons it) ----
    for (int i = tid; i < NA * 17; i += NT) out[i] = 0.0f;

    // ---- phase 1: sigmoid scores + validity only (stable by anchor idx) ----
    const int base = tid * PER;
    float sc[PER];
    int vmask = 0, cnt = 0;
    #pragma unroll
    for (int a = 0; a < PER; ++a) {
        float x = raw_scores[base + a];
        x = fminf(fmaxf(x, -100.0f), 100.0f);
        sc[a] = 1.0f / (1.0f + expf(-x));           // precise sigmoid
        bool v = (sc[a] >= MIN_SCORE);
        vmask |= (int)v << a;
        cnt += (int)v;
    }
    int incl = cnt;
    #pragma unroll
    for (int d = 1; d < 32; d <<= 1) {
        int v = __shfl_up_sync(FULLM, incl, d);
        if (lane >= d) incl += v;
    }
    if (lane == 31) s_wsum[wrp] = incl;
    __syncthreads();
    if (tid == 0) {
        int s = 0;
        #pragma unroll
        for (int w = 0; w < 4; ++w) { int t = s_wsum[w]; s_wsum[w] = s; s += t; }
        s_misc[0] = s;     // V
    }
    __syncthreads();
    const int V = s_misc[0];

    if (V > 0) {
        int off = s_wsum[wrp] + incl - cnt;          // exclusive offset
        #pragma unroll
        for (int a = 0; a < PER; ++a) {
            if (vmask & (1 << a)) {
                s_key[off]  = sc[a];
                s_sidx[off] = base + a;
                ++off;
            }
        }

        int P = 2;
        while (P < V) P <<= 1;                       // next pow2 >= V (<=1024)
        for (int i = V + tid; i < P; i += NT) { s_key[i] = NINF; s_sidx[i] = 100000 + i; }
        __syncthreads();

        // ---- phase 2: bitonic sort (score desc, anchor idx asc) ----
        for (int k = 2; k <= P; k <<= 1) {
            for (int j = k >> 1; j > 0; j >>= 1) {
                for (int i = tid; i < P; i += NT) {
                    int ixj = i ^ j;
                    if (ixj > i) {
                        float ki = s_key[i], kj = s_key[ixj];
                        int   ii = s_sidx[i], ij = s_sidx[ixj];
                        bool before = (ki > kj) || (ki == kj && ii < ij);
                        bool dirUp  = ((i & k) == 0);
                        if (dirUp ? !before : before) {
                            s_key[i] = kj; s_key[ixj] = ki;
                            s_sidx[i] = ij; s_sidx[ixj] = ii;
                        }
                    }
                }
                __syncthreads();
            }
        }

        // ---- phase 3a: decode ONLY the V sorted dets (pos-indexed) ----
        const int W = (V + 31) >> 5;
        const float inv = 1.0f / 128.0f;
        for (int pos = tid; pos < V; pos += NT) {
            const int anc = s_sidx[pos];
            const float4* rb4 = reinterpret_cast<const float4*>(raw_boxes + (size_t)anc * 16);
            float4 r0 = rb4[0], r1 = rb4[1], r2 = rb4[2], r3 = rb4[3];
            float4 an = reinterpret_cast<const float4*>(anchors)[anc];
            const float ax = an.x, ay = an.y, aw = an.z, ah = an.w;

            float xc = r0.x * inv * aw + ax;
            float yc = r0.y * inv * ah + ay;
            float w  = r0.z * inv * aw;
            float h  = r0.w * inv * ah;

            float* d = s_det + pos * 17;
            float c0 = yc - h * 0.5f;
            float c1 = xc - w * 0.5f;
            float c2 = yc + h * 0.5f;
            float c3 = xc + w * 0.5f;
            d[0] = c0; d[1] = c1; d[2] = c2; d[3] = c3;
            d[4]  = r1.x * inv * aw + ax;  d[5]  = r1.y * inv * ah + ay;
            d[6]  = r1.z * inv * aw + ax;  d[7]  = r1.w * inv * ah + ay;
            d[8]  = r2.x * inv * aw + ax;  d[9]  = r2.y * inv * ah + ay;
            d[10] = r2.z * inv * aw + ax;  d[11] = r2.w * inv * ah + ay;
            d[12] = r3.x * inv * aw + ax;  d[13] = r3.y * inv * ah + ay;
            d[14] = r3.z * inv * aw + ax;  d[15] = r3.w * inv * ah + ay;
            d[16] = s_key[pos];

            s_sbox[pos] = make_float4(c0, c1, c2, c3);
            s_sarea[pos] = (c2 - c0) * (c3 - c1);
        }
        __syncthreads();

        // ---- phase 3b: overlap bit-matrix (row per thread) ----
        for (int row = tid; row < V; row += NT) {
            const float4 b = s_sbox[row];
            const float areaA = s_sarea[row];
            unsigned word = 0;
            for (int j = 0; j < V; ++j) {
                const float4 c = s_sbox[j];
                float iy = fminf(b.z, c.z) - fmaxf(b.x, c.x);
                float ix = fminf(b.w, c.w) - fmaxf(b.y, c.y);
                iy = fmaxf(iy, 0.0f); ix = fmaxf(ix, 0.0f);
                float inter = iy * ix;
                float uni   = areaA + s_sarea[j] - inter;
                // iou > T  <=>  inter > T*uni   (uni>=0; uni==0 -> false, matches NaN>T)
                bool ov = (inter > IOU_T * uni);
                word |= (unsigned)ov << (j & 31);
                if ((j & 31) == 31) { s_mask[row * W + (j >> 5)] = word; word = 0; }
            }
            if (V & 31) s_mask[row * W + (V >> 5)] = word;
        }
        __syncthreads();

        // ---- phase 4: warp-register scan (warp 0 only) ----
        if (wrp == 0) {
            unsigned rem = 0;
            if (lane < W) {
                int rb = V - (lane << 5);
                rem = (rb >= 32) ? FULLM : ((1u << rb) - 1u);
            }
            int count = 0;
            while (true) {
                unsigned nz = __ballot_sync(FULLM, rem != 0u);
                if (nz == 0u) break;
                const int w0  = __ffs(nz) - 1;
                const unsigned rw = __shfl_sync(FULLM, rem, w0);
                const int b   = __ffs(rw) - 1;
                const int pos = (w0 << 5) + b;

                unsigned mrow = (lane < W) ? s_mask[pos * W + lane] : 0u;
                unsigned ovw  = mrow & rem;
                rem &= ~mrow;
                if (lane == w0) rem &= ~(1u << b);   // ensure best removed

                unsigned ov_noself = ovw;
                if (lane == w0) ov_noself &= ~(1u << b);
                const unsigned anyov = __ballot_sync(FULLM, ov_noself != 0u);

                if (anyov) {
                    const int n = (int)__reduce_add_sync(FULLM, (unsigned)__popc(ovw));
                    if (lane < W) s_ov[lane] = ovw;
                    __syncwarp(FULLM);
                    if (n > 1 && lane == 0) {
                        float acc[16];
                        #pragma unroll
                        for (int c = 0; c < 16; ++c) acc[c] = 0.0f;
                        float tot = 0.0f;
                        for (int w = 0; w < W; ++w) {
                            unsigned m = s_ov[w];
                            while (m) {
                                int bb = __ffs(m) - 1; m &= m - 1;
                                const int pos2 = (w << 5) + bb;
                                const float s = s_det[pos2 * 17 + 16];
                                #pragma unroll
                                for (int c = 0; c < 16; ++c) acc[c] += s * s_det[pos2 * 17 + c];
                                tot += s;
                            }
                        }
                        const float denom = (tot > 0.0f) ? tot : 1.0f;
                        #pragma unroll
                        for (int c = 0; c < 16; ++c) s_det[pos * 17 + c] = acc[c] / denom;
                        s_det[pos * 17 + 16] = tot / (float)n;
                    }
                    __syncwarp(FULLM);               // s_ov settled before next overwrite
                }

                if (lane == 0) s_sel[count] = pos;
                ++count;
            }
            if (lane == 0) s_misc[1] = count;
        }
        __syncthreads();

        // ---- phase 5: parallel copy of selected rows ----
        const int count = s_misc[1];
        for (int e = tid; e < count * 17; e += NT) {
            const int k = e / 17, c = e - k * 17;
            out[e] = s_det[s_sel[k] * 17 + c];
        }
    }
}

extern "C" void kernel_launch(void* const* d_in, const int* in_sizes, int n_in,
                              void* d_out, int out_size) {
    // identify inputs by size (robust to ordering):
    //   raw_boxes: 2048*896*16, raw_scores: 2048*896, anchors: 896*4
    const float* raw_boxes  = nullptr;
    const float* raw_scores = nullptr;
    const float* anchors    = nullptr;
    for (int i = 0; i < n_in; ++i) {
        if (in_sizes[i] == NA * 4)            anchors    = (const float*)d_in[i];
        else if (in_sizes[i] == 2048 * NA)    raw_scores = (const float*)d_in[i];
        else                                  raw_boxes  = (const float*)d_in[i];
    }
    cudaFuncSetAttribute(blazeface_nms_kernel,
                         cudaFuncAttributeMaxDynamicSharedMemorySize, SMEM_BYTES);
    blazeface_nms_kernel<<<1, NT, SMEM_BYTES>>>(raw_boxes, raw_scores, anchors, (float*)d_out);
}

// round 17
// speedup vs baseline: 8.2228x; 1.0156x over previous
#include <cuda_runtime.h>

// BlazeFace decode + weighted NMS (batch 0 only), mask-matrix formulation.
// Single block, 128 threads. Deferred decode + SCALAR REGISTER SCAN:
// for V <= 128 (W <= 4) the remaining-set lives in two 64-bit registers of
// thread 0 -- per step: ffsll -> one LDS.128 mask row -> AND-NOT. No warp
// collectives on the serial chain. W > 4 falls back to the warp scan.

#define NA    896
#define NT    128
#define PER   7           // NA / NT
#define WMAX  28          // ceil(NA/32)
#define IOU_T 0.3f
#define MIN_SCORE 0.75f
#define FULLM 0xffffffffu

// shared layout in 4-byte units (s_det indexed by SORTED POSITION)
#define OFF_DET    0                        // NA*17  det rows (pos-indexed)
#define OFF_KEY    (OFF_DET  + NA*17)       // 1024   sort keys
#define OFF_SIDX   (OFF_KEY  + 1024)        // 1024   anchor idx (int)
#define OFF_SBOX   (OFF_SIDX + 1024)        // NA*4   per-pos boxes (16B aligned)
#define OFF_SAREA  (OFF_SBOX + NA*4)        // NA     per-pos areas
#define OFF_MASK   (OFF_SAREA + NA)         // NA*WMAX overlap bits (16B aligned)
#define OFF_SEL    (OFF_MASK + NA*WMAX)     // NA     selected pos (int)
#define OFF_OV     (OFF_SEL  + NA)          // WMAX   overlap scratch
#define OFF_WSUM   (OFF_OV   + WMAX)        // 4      warp scan sums (int)
#define OFF_MISC   (OFF_WSUM + 4)           // 2      [V, count] (int)
#define SMEM_UNITS (OFF_MISC + 2)
#define SMEM_BYTES (SMEM_UNITS * 4)

__device__ __forceinline__ float neg_inf() { return __int_as_float(0xff800000); }

__global__ __launch_bounds__(NT, 1)
void blazeface_nms_kernel(const float* __restrict__ raw_boxes,
                          const float* __restrict__ raw_scores,
                          const float* __restrict__ anchors,
                          float* __restrict__ out)
{
    extern __shared__ float smem[];
    float* s_det   = smem + OFF_DET;
    float* s_key   = smem + OFF_KEY;
    int*   s_sidx  = (int*)(smem + OFF_SIDX);
    float4* s_sbox = (float4*)(smem + OFF_SBOX);
    float* s_sarea = smem + OFF_SAREA;
    unsigned* s_mask = (unsigned*)(smem + OFF_MASK);
    int*   s_sel   = (int*)(smem + OFF_SEL);
    unsigned* s_ov = (unsigned*)(smem + OFF_OV);
    int*   s_wsum  = (int*)(smem + OFF_WSUM);
    int*   s_misc  = (int*)(smem + OFF_MISC);   // [0]=V, [1]=count

    const int tid  = threadIdx.x;
    const int lane = tid & 31;
    const int wrp  = tid >> 5;
    const float NINF = neg_inf();

    // ---- zero output (harness poisons it) ----
    for (int i = tid; i < NA * 17; i += NT) out[i] = 0.0f;

    // ---- phase 1: sigmoid scores + validity only (stable by anchor idx) ----
    const int base = tid * PER;
    float sc[PER];
    int vmask = 0, cnt = 0;
    #pragma unroll
    for (int a = 0; a < PER; ++a) {
        float x = raw_scores[base + a];
        x = fminf(fmaxf(x, -100.0f), 100.0f);
        sc[a] = 1.0f / (1.0f + expf(-x));           // precise sigmoid
        bool v = (sc[a] >= MIN_SCORE);
        vmask |= (int)v << a;
        cnt += (int)v;
    }
    int incl = cnt;
    #pragma unroll
    for (int d = 1; d < 32; d <<= 1) {
        int v = __shfl_up_sync(FULLM, incl, d);
        if (lane >= d) incl += v;
    }
    if (lane == 31) s_wsum[wrp] = incl;
    __syncthreads();
    if (tid == 0) {
        int s = 0;
        #pragma unroll
        for (int w = 0; w < 4; ++w) { int t = s_wsum[w]; s_wsum[w] = s; s += t; }
        s_misc[0] = s;     // V
    }
    __syncthreads();
    const int V = s_misc[0];

    if (V > 0) {
        int off = s_wsum[wrp] + incl - cnt;          // exclusive offset
        #pragma unroll
        for (int a = 0; a < PER; ++a) {
            if (vmask & (1 << a)) {
                s_key[off]  = sc[a];
                s_sidx[off] = base + a;
                ++off;
            }
        }

        int P = 2;
        while (P < V) P <<= 1;                       // next pow2 >= V (<=1024)
        for (int i = V + tid; i < P; i += NT) { s_key[i] = NINF; s_sidx[i] = 100000 + i; }
        __syncthreads();

        // ---- phase 2: bitonic sort (score desc, anchor idx asc) ----
        for (int k = 2; k <= P; k <<= 1) {
            for (int j = k >> 1; j > 0; j >>= 1) {
                for (int i = tid; i < P; i += NT) {
                    int ixj = i ^ j;
                    if (ixj > i) {
                        float ki = s_key[i], kj = s_key[ixj];
                        int   ii = s_sidx[i], ij = s_sidx[ixj];
                        bool before = (ki > kj) || (ki == kj && ii < ij);
                        bool dirUp  = ((i & k) == 0);
                        if (dirUp ? !before : before) {
                            s_key[i] = kj; s_key[ixj] = ki;
                            s_sidx[i] = ij; s_sidx[ixj] = ii;
                        }
                    }
                }
                __syncthreads();
            }
        }

        // ---- phase 3a: decode ONLY the V sorted dets (pos-indexed) ----
        const int W  = (V + 31) >> 5;
        const int SW = (W <= 4) ? 4 : W;             // mask row stride (pad to uint4)
        const float inv = 1.0f / 128.0f;
        for (int pos = tid; pos < V; pos += NT) {
            const int anc = s_sidx[pos];
            const float4* rb4 = reinterpret_cast<const float4*>(raw_boxes + (size_t)anc * 16);
            float4 r0 = rb4[0], r1 = rb4[1], r2 = rb4[2], r3 = rb4[3];
            float4 an = reinterpret_cast<const float4*>(anchors)[anc];
            const float ax = an.x, ay = an.y, aw = an.z, ah = an.w;

            float xc = r0.x * inv * aw + ax;
            float yc = r0.y * inv * ah + ay;
            float w  = r0.z * inv * aw;
            float h  = r0.w * inv * ah;

            float* d = s_det + pos * 17;
            float c0 = yc - h * 0.5f;
            float c1 = xc - w * 0.5f;
            float c2 = yc + h * 0.5f;
            float c3 = xc + w * 0.5f;
            d[0] = c0; d[1] = c1; d[2] = c2; d[3] = c3;
            d[4]  = r1.x * inv * aw + ax;  d[5]  = r1.y * inv * ah + ay;
            d[6]  = r1.z * inv * aw + ax;  d[7]  = r1.w * inv * ah + ay;
            d[8]  = r2.x * inv * aw + ax;  d[9]  = r2.y * inv * ah + ay;
            d[10] = r2.z * inv * aw + ax;  d[11] = r2.w * inv * ah + ay;
            d[12] = r3.x * inv * aw + ax;  d[13] = r3.y * inv * ah + ay;
            d[14] = r3.z * inv * aw + ax;  d[15] = r3.w * inv * ah + ay;
            d[16] = s_key[pos];

            s_sbox[pos] = make_float4(c0, c1, c2, c3);
            s_sarea[pos] = (c2 - c0) * (c3 - c1);
        }
        __syncthreads();

        // ---- phase 3b: overlap bit-matrix (row per thread, stride SW) ----
        for (int row = tid; row < V; row += NT) {
            const float4 b = s_sbox[row];
            const float areaA = s_sarea[row];
            unsigned word = 0;
            for (int j = 0; j < V; ++j) {
                const float4 c = s_sbox[j];
                float iy = fminf(b.z, c.z) - fmaxf(b.x, c.x);
                float ix = fminf(b.w, c.w) - fmaxf(b.y, c.y);
                iy = fmaxf(iy, 0.0f); ix = fmaxf(ix, 0.0f);
                float inter = iy * ix;
                float uni   = areaA + s_sarea[j] - inter;
                // iou > T  <=>  inter > T*uni   (uni>=0; uni==0 -> false, matches NaN>T)
                bool ov = (inter > IOU_T * uni);
                word |= (unsigned)ov << (j & 31);
                if ((j & 31) == 31) { s_mask[row * SW + (j >> 5)] = word; word = 0; }
            }
            if (V & 31) s_mask[row * SW + (V >> 5)] = word;
            for (int w = W; w < SW; ++w) s_mask[row * SW + w] = 0u;  // zero-pad
        }
        __syncthreads();

        // ---- phase 4: NMS scan ----
        if (W <= 4) {
            // scalar register scan: remaining-set in two 64-bit regs of thread 0
            if (tid == 0) {
                unsigned long long r01 = (V >= 64) ? ~0ull : ((1ull << V) - 1ull);
                const int v2 = V - 64;
                unsigned long long r23 = (v2 <= 0) ? 0ull
                                       : ((v2 >= 64) ? ~0ull : ((1ull << v2) - 1ull));
                int count = 0;
                while (r01 | r23) {
                    const int pos = r01 ? (__ffsll((long long)r01) - 1)
                                        : (64 + __ffsll((long long)r23) - 1);
                    const uint4 m = *reinterpret_cast<const uint4*>(s_mask + pos * 4);
                    const unsigned long long m01 = (unsigned long long)m.x
                                                 | ((unsigned long long)m.y << 32);
                    const unsigned long long m23 = (unsigned long long)m.z
                                                 | ((unsigned long long)m.w << 32);
                    const unsigned long long ov01 = m01 & r01;
                    const unsigned long long ov23 = m23 & r23;
                    r01 &= ~m01; r23 &= ~m23;
                    unsigned long long self01 = 0ull, self23 = 0ull;
                    if (pos < 64) self01 = 1ull << pos; else self23 = 1ull << (pos - 64);
                    r01 &= ~self01; r23 &= ~self23;    // ensure best removed

                    if ((ov01 & ~self01) | (ov23 & ~self23)) {
                        const int n = __popcll(ov01) + __popcll(ov23);
                        if (n > 1) {
                            float acc[16];
                            #pragma unroll
                            for (int c = 0; c < 16; ++c) acc[c] = 0.0f;
                            float tot = 0.0f;
                            unsigned long long mm = ov01;
                            while (mm) {
                                int bb = __ffsll((long long)mm) - 1; mm &= mm - 1;
                                const float s = s_det[bb * 17 + 16];
                                #pragma unroll
                                for (int c = 0; c < 16; ++c) acc[c] += s * s_det[bb * 17 + c];
                                tot += s;
                            }
                            mm = ov23;
                            while (mm) {
                                int bb = 64 + __ffsll((long long)mm) - 1; mm &= mm - 1;
                                const float s = s_det[bb * 17 + 16];
                                #pragma unroll
                                for (int c = 0; c < 16; ++c) acc[c] += s * s_det[bb * 17 + c];
                                tot += s;
                            }
                            const float denom = (tot > 0.0f) ? tot : 1.0f;
                            #pragma unroll
                            for (int c = 0; c < 16; ++c) s_det[pos * 17 + c] = acc[c] / denom;
                            s_det[pos * 17 + 16] = tot / (float)n;
                        }
                    }
                    s_sel[count++] = pos;
                }
                s_misc[1] = count;
            }
        } else {
            // warp scan fallback (V > 128); stride SW == W here
            if (wrp == 0) {
                unsigned rem = 0;
                if (lane < W) {
                    int rb = V - (lane << 5);
                    rem = (rb >= 32) ? FULLM : ((1u << rb) - 1u);
                }
                int count = 0;
                while (true) {
                    unsigned nz = __ballot_sync(FULLM, rem != 0u);
                    if (nz == 0u) break;
                    const int w0  = __ffs(nz) - 1;
                    const unsigned rw = __shfl_sync(FULLM, rem, w0);
                    const int b   = __ffs(rw) - 1;
                    const int pos = (w0 << 5) + b;

                    unsigned mrow = (lane < W) ? s_mask[pos * SW + lane] : 0u;
                    unsigned ovw  = mrow & rem;
                    rem &= ~mrow;
                    if (lane == w0) rem &= ~(1u << b);

                    unsigned ov_noself = ovw;
                    if (lane == w0) ov_noself &= ~(1u << b);
                    const unsigned anyov = __ballot_sync(FULLM, ov_noself != 0u);

                    if (anyov) {
                        const int n = (int)__reduce_add_sync(FULLM, (unsigned)__popc(ovw));
                        if (lane < W) s_ov[lane] = ovw;
                        __syncwarp(FULLM);
                        if (n > 1 && lane == 0) {
                            float acc[16];
                            #pragma unroll
                            for (int c = 0; c < 16; ++c) acc[c] = 0.0f;
                            float tot = 0.0f;
                            for (int w = 0; w < W; ++w) {
                                unsigned m = s_ov[w];
                                while (m) {
                                    int bb = __ffs(m) - 1; m &= m - 1;
                                    const int pos2 = (w << 5) + bb;
                                    const float s = s_det[pos2 * 17 + 16];
                                    #pragma unroll
                                    for (int c = 0; c < 16; ++c) acc[c] += s * s_det[pos2 * 17 + c];
                                    tot += s;
                                }
                            }
                            const float denom = (tot > 0.0f) ? tot : 1.0f;
                            #pragma unroll
                            for (int c = 0; c < 16; ++c) s_det[pos * 17 + c] = acc[c] / denom;
                            s_det[pos * 17 + 16] = tot / (float)n;
                        }
                        __syncwarp(FULLM);
                    }

                    if (lane == 0) s_sel[count] = pos;
                    ++count;
                }
                if (lane == 0) s_misc[1] = count;
            }
        }
        __syncthreads();

        // ---- phase 5: parallel copy of selected rows ----
        const int count = s_misc[1];
        for (int e = tid; e < count * 17; e += NT) {
            const int k = e / 17, c = e - k * 17;
            out[e] = s_det[s_sel[k] * 17 + c];
        }
    }
}

extern "C" void kernel_launch(void* const* d_in, const int* in_sizes, int n_in,
                              void* d_out, int out_size) {
    // identify inputs by size (robust to ordering):
    //   raw_boxes: 2048*896*16, raw_scores: 2048*896, anchors: 896*4
    const float* raw_boxes  = nullptr;
    const float* raw_scores = nullptr;
    const float* anchors    = nullptr;
    for (int i = 0; i < n_in; ++i) {
        if (in_sizes[i] == NA * 4)            anchors    = (const float*)d_in[i];
        else if (in_sizes[i] == 2048 * NA)    raw_scores = (const float*)d_in[i];
        else                                  raw_boxes  = (const float*)d_in[i];
    }
    cudaFuncSetAttribute(blazeface_nms_kernel,
                         cudaFuncAttributeMaxDynamicSharedMemorySize, SMEM_BYTES);
    blazeface_nms_kernel<<<1, NT, SMEM_BYTES>>>(raw_boxes, raw_scores, anchors, (float*)d_out);
}